// round 3
// baseline (speedup 1.0000x reference)
#include <cuda_runtime.h>
#include <math.h>

#define NN 2592
#define BB 128
#define LL 64
#define CC 16
#define CHO 64

// ---------------- scratch (device globals; no allocation) ----------------
__device__ float g_uhat[(size_t)NN * BB * LL];   // [n][b][l]  ~85 MB
__device__ float g_S0[BB * LL];                  // sum_n u_hat
__device__ float g_s1[BB * LL];
__device__ float g_s2[BB * LL];
__device__ float g_b1[NN];
__device__ float g_b2[NN];
__device__ float g_nrm2[(size_t)NN * BB];        // [n][b] : sum_l u_hat^2
__device__ float g_unorm[(size_t)BB * NN];       // [b][n] : c2[n]*||u_hat||

__device__ __forceinline__ float squashf(float s) {
    float sq = s * s;
    // sq*s / ((1+sq)*sqrt(sq)) == s*|s|/(1+sq)
    return s * fabsf(s) / (1.0f + sq);
}

// ---------------- K0: zero accumulators ----------------
__global__ void kzero() {
    int i = blockIdx.x * 256 + threadIdx.x;
    if (i < BB * LL) { g_S0[i] = 0.f; g_s1[i] = 0.f; g_s2[i] = 0.f; }
}

// ---------------- K1: u_hat + S0 (sum over n) + nrm2 ----------------
// grid 162 (16 n per CTA), 256 threads. Per n: 128x64 = x[:,n,:](128x16) @ W[n]^T(16x64)
__global__ void __launch_bounds__(256) k1_uhat(const float* __restrict__ x,
                                               const float* __restrict__ W) {
    __shared__ float xs[CC][BB];       // c-major x tile
    __shared__ float Ws[CC][LL];       // c-major W tile
    __shared__ float ps[CC][BB + 1];   // sumsq partials, padded vs bank conflicts

    int t = threadIdx.x;
    int n0 = blockIdx.x * 16;
    int bg = t >> 4, lq = t & 15;
    int bbase = bg * 8;

    float s_acc[8][4];
#pragma unroll
    for (int i = 0; i < 8; i++)
#pragma unroll
        for (int j = 0; j < 4; j++) s_acc[i][j] = 0.f;

    for (int nn = 0; nn < 16; nn++) {
        int n = n0 + nn;
        // load x[:, n, :] -> xs[c][b]
        {
            int b = t & 127, half = t >> 7;
            const float4* xp = reinterpret_cast<const float4*>(x + ((size_t)b * NN + n) * CC) + half * 2;
            float4 a = xp[0], c4 = xp[1];
            int cb = half * 8;
            xs[cb + 0][b] = a.x;  xs[cb + 1][b] = a.y;  xs[cb + 2][b] = a.z;  xs[cb + 3][b] = a.w;
            xs[cb + 4][b] = c4.x; xs[cb + 5][b] = c4.y; xs[cb + 6][b] = c4.z; xs[cb + 7][b] = c4.w;
        }
        // load W[n] -> Ws[c][l]
        {
            int l = t & 63, cq = t >> 6;
            const float4* wp = reinterpret_cast<const float4*>(W + ((size_t)n * LL + l) * CC + cq * 4);
            float4 a = wp[0];
            Ws[cq * 4 + 0][l] = a.x; Ws[cq * 4 + 1][l] = a.y;
            Ws[cq * 4 + 2][l] = a.z; Ws[cq * 4 + 3][l] = a.w;
        }
        __syncthreads();

        float acc[8][4];
#pragma unroll
        for (int i = 0; i < 8; i++)
#pragma unroll
            for (int j = 0; j < 4; j++) acc[i][j] = 0.f;

#pragma unroll
        for (int c = 0; c < CC; c++) {
            float4 xa = *reinterpret_cast<const float4*>(&xs[c][bbase]);
            float4 xb = *reinterpret_cast<const float4*>(&xs[c][bbase + 4]);
            float4 wv = *reinterpret_cast<const float4*>(&Ws[c][lq * 4]);
            float xr[8] = {xa.x, xa.y, xa.z, xa.w, xb.x, xb.y, xb.z, xb.w};
            float wr[4] = {wv.x, wv.y, wv.z, wv.w};
#pragma unroll
            for (int i = 0; i < 8; i++)
#pragma unroll
                for (int j = 0; j < 4; j++) acc[i][j] += xr[i] * wr[j];
        }

        float* ub = g_uhat + (size_t)n * BB * LL;
#pragma unroll
        for (int i = 0; i < 8; i++) {
            int b = bbase + i;
            float4 o = make_float4(acc[i][0], acc[i][1], acc[i][2], acc[i][3]);
            *reinterpret_cast<float4*>(ub + b * LL + lq * 4) = o;
            ps[lq][b] = acc[i][0] * acc[i][0] + acc[i][1] * acc[i][1] +
                        acc[i][2] * acc[i][2] + acc[i][3] * acc[i][3];
            s_acc[i][0] += acc[i][0]; s_acc[i][1] += acc[i][1];
            s_acc[i][2] += acc[i][2]; s_acc[i][3] += acc[i][3];
        }
        __syncthreads();
        if (t < BB) {
            float nr = 0.f;
#pragma unroll
            for (int q = 0; q < 16; q++) nr += ps[q][t];
            g_nrm2[(size_t)n * BB + t] = nr;
        }
        // second sync: orders ps readers above vs next iteration's writers
        __syncthreads();
    }

#pragma unroll
    for (int i = 0; i < 8; i++)
#pragma unroll
        for (int j = 0; j < 4; j++)
            atomicAdd(&g_S0[(bbase + i) * LL + lq * 4 + j], s_acc[i][j]);
}

// ---------------- a-pass: b_out[n] = b_prev[n] + mean_b( u_hat[b,n,:] . v[b,:] ) ----------------
// v computed on the fly: v = squash(sIn * sscale). grid 324 (8 n per CTA, warp per n).
__global__ void __launch_bounds__(256) k_apass(int mode) {
    const float* sIn = (mode == 0) ? g_S0 : g_s1;
    float sscale = (mode == 0) ? (1.0f / NN) : 1.0f;

    __shared__ float vs[BB * LL];   // 32 KB
    int t = threadIdx.x;
    for (int i = t; i < BB * LL; i += 256) vs[i] = squashf(sIn[i] * sscale);
    __syncthreads();

    int w = t >> 5, lane = t & 31;
    int n = blockIdx.x * 8 + w;
    const float2* up = reinterpret_cast<const float2*>(g_uhat + (size_t)n * BB * LL);
    const float2* vp = reinterpret_cast<const float2*>(vs);
    float acc = 0.f;
#pragma unroll 4
    for (int b = 0; b < BB; b++) {
        float2 u = up[b * 32 + lane];
        float2 vv = vp[b * 32 + lane];
        acc += u.x * vv.x;
        acc += u.y * vv.y;
    }
#pragma unroll
    for (int off = 16; off; off >>= 1) acc += __shfl_xor_sync(0xffffffffu, acc, off);
    if (lane == 0) {
        float bprev = (mode == 0) ? 0.f : g_b1[n];
        float* bo = (mode == 0) ? g_b1 : g_b2;
        bo[n] = bprev + acc * (1.0f / BB);
    }
}

// ---------------- s-pass: c = softmax(bIn) computed per-CTA; sOut += sum_n c[n]*u_hat ----------------
// mode==1 additionally writes u_norm[b][n] = c2[n]*sqrt(nrm2[n][b]). grid 324.
__global__ void __launch_bounds__(256) k_spass(int mode) {
    const float* bIn = (mode == 0) ? g_b1 : g_b2;
    float* sOut = (mode == 0) ? g_s1 : g_s2;

    __shared__ float red[256];
    __shared__ float cs[8];
    int t = threadIdx.x;

    float m = -3.0e38f;
    for (int i = t; i < NN; i += 256) m = fmaxf(m, bIn[i]);
    red[t] = m; __syncthreads();
    for (int s = 128; s; s >>= 1) { if (t < s) red[t] = fmaxf(red[t], red[t + s]); __syncthreads(); }
    float mx = red[0]; __syncthreads();

    float sm = 0.f;
    for (int i = t; i < NN; i += 256) sm += __expf(bIn[i] - mx);
    red[t] = sm; __syncthreads();
    for (int s = 128; s; s >>= 1) { if (t < s) red[t] += red[t + s]; __syncthreads(); }
    float denom = red[0]; __syncthreads();

    if (t < 8) cs[t] = __expf(bIn[blockIdx.x * 8 + t] - mx) / denom;
    __syncthreads();

    if (mode == 1) {
        int nn = t >> 5, lane = t & 31;
        int n = blockIdx.x * 8 + nn;
        float cv = cs[nn];
#pragma unroll
        for (int i = 0; i < 4; i++) {
            int b = lane + 32 * i;
            g_unorm[(size_t)b * NN + n] = cv * sqrtf(g_nrm2[(size_t)n * BB + b]);
        }
    }

    int bg = t >> 4, lq = t & 15;
    float acc[8][4];
#pragma unroll
    for (int i = 0; i < 8; i++)
#pragma unroll
        for (int j = 0; j < 4; j++) acc[i][j] = 0.f;

#pragma unroll
    for (int nn = 0; nn < 8; nn++) {
        int n = blockIdx.x * 8 + nn;
        float cv = cs[nn];
        const float4* up = reinterpret_cast<const float4*>(g_uhat + (size_t)n * BB * LL);
#pragma unroll
        for (int i = 0; i < 8; i++) {
            float4 u = up[(bg * 8 + i) * 16 + lq];
            acc[i][0] += cv * u.x; acc[i][1] += cv * u.y;
            acc[i][2] += cv * u.z; acc[i][3] += cv * u.w;
        }
    }
#pragma unroll
    for (int i = 0; i < 8; i++)
#pragma unroll
        for (int j = 0; j < 4; j++)
            atomicAdd(&sOut[(bg * 8 + i) * LL + lq * 4 + j], acc[i][j]);
}

// ---------------- K6: v_j output + ConvTranspose2d ----------------
// blocks [0,2048): (b,oh) conv tiles. blocks [2048,2080): v_j = squash(s2).
__global__ void __launch_bounds__(256) k6_out(const float* __restrict__ cw,
                                              const float* __restrict__ cb,
                                              float* __restrict__ out) {
    int t = threadIdx.x;
    if (blockIdx.x >= 2048) {
        int idx = (blockIdx.x - 2048) * 256 + t;   // 32*256 = 8192
        out[idx] = squashf(g_s2[idx]);
        return;
    }
    int b = blockIdx.x >> 4, oh = blockIdx.x & 15;
    __shared__ float ws[32][64][2];   // ws[ic][oc][j] = conv_w[ic][oc][1-kh][j]
    __shared__ float un[32][9];
    __shared__ float bias[CHO];

    int kh = oh & 1;
    int ih = (oh + kh) >> 1;

    for (int i = t; i < 32 * 64 * 2; i += 256) {
        int ic = i >> 7, r = i & 127, oc = r >> 1, j = r & 1;
        ws[ic][oc][j] = cw[ic * 256 + oc * 4 + (1 - kh) * 2 + j];
    }
    for (int i = t; i < 288; i += 256) {
        int ic = i / 9, iw = i - ic * 9;
        un[ic][iw] = g_unorm[(size_t)b * NN + ic * 81 + ih * 9 + iw];
    }
    if (t < CHO) bias[t] = cb[t];
    __syncthreads();

    int ow = t & 15, ocg = t >> 4;
    int kw = ow & 1;
    int iw = (ow + kw) >> 1;
    int j = 1 - kw;
    size_t obase = 8192 + (((size_t)b * CHO) * 16 + oh) * 16 + ow;
#pragma unroll
    for (int q = 0; q < 4; q++) {
        int oc = ocg * 4 + q;
        float acc = bias[oc];
#pragma unroll
        for (int ic = 0; ic < 32; ic++) acc += un[ic][iw] * ws[ic][oc][j];
        out[obase + (size_t)oc * 256] = acc;
    }
}

// ---------------- launch ----------------
extern "C" void kernel_launch(void* const* d_in, const int* in_sizes, int n_in,
                              void* d_out, int out_size) {
    const float* x  = (const float*)d_in[0];   // (128, 2592, 16)
    const float* W  = (const float*)d_in[1];   // (1, 2592, 1, 64, 16)
    const float* cw = (const float*)d_in[2];   // (32, 64, 2, 2)
    const float* cb = (const float*)d_in[3];   // (64,)
    float* out = (float*)d_out;                // 8192 (v_j) + 2097152 (out_img)

    kzero<<<32, 256>>>();
    k1_uhat<<<162, 256>>>(x, W);   // u_hat + S0 + nrm2
    k_apass<<<324, 256>>>(0);      // v0=squash(S0/N); b1 = mean_b <u_hat, v0>
    k_spass<<<324, 256>>>(0);      // c1=softmax(b1); s1 = sum c1*u_hat
    k_apass<<<324, 256>>>(1);      // v1=squash(s1);  b2 = b1 + mean_b <u_hat, v1>
    k_spass<<<324, 256>>>(1);      // c2=softmax(b2); s2; u_norm = c2*||u_hat||
    k6_out<<<2080, 256>>>(cw, cb, out);  // v_j = squash(s2); ConvT -> out_img
}

// round 5
// speedup vs baseline: 1.5276x; 1.5276x over previous
#include <cuda_runtime.h>
#include <math.h>

#define NN 2592
#define BB 128
#define LL 64
#define CC 16
#define CHO 64

// ---------------- scratch (device globals; no allocation) ----------------
__device__ float g_uhat[(size_t)NN * BB * LL];   // [n][b][l]  ~85 MB
__device__ float g_S0[BB * LL];                  // sum_n u_hat
__device__ float g_s1[BB * LL];
__device__ float g_s2[BB * LL];
__device__ float g_b1[NN];
__device__ float g_b2[NN];
__device__ float g_c2[NN];
__device__ float g_nrm2[(size_t)NN * BB];        // [n][b] : sum_l u_hat^2

__device__ __forceinline__ float squashf(float s) {
    float sq = s * s;
    return s * fabsf(s) / (1.0f + sq);   // == sq*s/((1+sq)*sqrt(sq))
}

__device__ __forceinline__ void red_add_v4(float* p, float a, float b, float c, float d) {
    asm volatile("red.global.add.v4.f32 [%0], {%1, %2, %3, %4};"
                 :: "l"(p), "f"(a), "f"(b), "f"(c), "f"(d) : "memory");
}

// ---------------- K0: zero accumulators (S0,s1,s2,b1,b2) ----------------
__global__ void kzero() {
    int i = blockIdx.x * 256 + threadIdx.x;
    if (i < BB * LL) { g_S0[i] = 0.f; g_s1[i] = 0.f; g_s2[i] = 0.f; }
    if (i < NN) { g_b1[i] = 0.f; g_b2[i] = 0.f; }
}

// ---------------- K1: u_hat + S0 (red.v4) + nrm2 ----------------
// grid 648 (4 n per CTA), 256 threads. Per n: (128b x 64l) = x[:,n,:](128x16) @ W[n]^T(16x64)
__global__ void __launch_bounds__(256) k1_uhat(const float* __restrict__ x,
                                               const float* __restrict__ W) {
    __shared__ float xs[CC][BB];       // c-major x tile (8 KB)
    __shared__ float Ws[CC][LL];       // c-major W tile (4 KB)
    __shared__ float ps[CC][BB + 1];   // sumsq partials

    int t = threadIdx.x;
    int n0 = blockIdx.x * 4;
    int bg = t >> 4, lq = t & 15;
    int bbase = bg * 8;

    float s_acc[8][4];
#pragma unroll
    for (int i = 0; i < 8; i++)
#pragma unroll
        for (int j = 0; j < 4; j++) s_acc[i][j] = 0.f;

#pragma unroll 1
    for (int nn = 0; nn < 4; nn++) {
        int n = n0 + nn;
        {   // x[:, n, :] -> xs[c][b]
            int b = t & 127, half = t >> 7;
            const float4* xp = reinterpret_cast<const float4*>(x + ((size_t)b * NN + n) * CC) + half * 2;
            float4 a = xp[0], c4 = xp[1];
            int cb = half * 8;
            xs[cb + 0][b] = a.x;  xs[cb + 1][b] = a.y;  xs[cb + 2][b] = a.z;  xs[cb + 3][b] = a.w;
            xs[cb + 4][b] = c4.x; xs[cb + 5][b] = c4.y; xs[cb + 6][b] = c4.z; xs[cb + 7][b] = c4.w;
        }
        {   // W[n] -> Ws[c][l]
            int l = t & 63, cq = t >> 6;
            const float4* wp = reinterpret_cast<const float4*>(W + ((size_t)n * LL + l) * CC + cq * 4);
            float4 a = wp[0];
            Ws[cq * 4 + 0][l] = a.x; Ws[cq * 4 + 1][l] = a.y;
            Ws[cq * 4 + 2][l] = a.z; Ws[cq * 4 + 3][l] = a.w;
        }
        __syncthreads();

        float acc[8][4];
#pragma unroll
        for (int i = 0; i < 8; i++)
#pragma unroll
            for (int j = 0; j < 4; j++) acc[i][j] = 0.f;

#pragma unroll
        for (int c = 0; c < CC; c++) {
            float4 xa = *reinterpret_cast<const float4*>(&xs[c][bbase]);
            float4 xb = *reinterpret_cast<const float4*>(&xs[c][bbase + 4]);
            float4 wv = *reinterpret_cast<const float4*>(&Ws[c][lq * 4]);
            float xr[8] = {xa.x, xa.y, xa.z, xa.w, xb.x, xb.y, xb.z, xb.w};
            float wr[4] = {wv.x, wv.y, wv.z, wv.w};
#pragma unroll
            for (int i = 0; i < 8; i++)
#pragma unroll
                for (int j = 0; j < 4; j++) acc[i][j] += xr[i] * wr[j];
        }

        float* ub = g_uhat + (size_t)n * BB * LL;
#pragma unroll
        for (int i = 0; i < 8; i++) {
            int b = bbase + i;
            *reinterpret_cast<float4*>(ub + b * LL + lq * 4) =
                make_float4(acc[i][0], acc[i][1], acc[i][2], acc[i][3]);
            ps[lq][b] = acc[i][0] * acc[i][0] + acc[i][1] * acc[i][1] +
                        acc[i][2] * acc[i][2] + acc[i][3] * acc[i][3];
            s_acc[i][0] += acc[i][0]; s_acc[i][1] += acc[i][1];
            s_acc[i][2] += acc[i][2]; s_acc[i][3] += acc[i][3];
        }
        __syncthreads();
        if (t < BB) {
            float nr = 0.f;
#pragma unroll
            for (int q = 0; q < 16; q++) nr += ps[q][t];
            g_nrm2[(size_t)n * BB + t] = nr;
        }
        __syncthreads();   // ps readers vs next-iter writers
    }

#pragma unroll
    for (int i = 0; i < 8; i++)
        red_add_v4(&g_S0[(bbase + i) * LL + lq * 4],
                   s_acc[i][0], s_acc[i][1], s_acc[i][2], s_acc[i][3]);
}

// ---------------- a-pass ----------------
// b_out[n] += (1/B) * sum_{b in tile} <u_hat[b,n,:], v[b,:]>,  v = squash(sIn*scale)
// grid 1296 = 324 n-tiles (8 n) x 4 b-tiles (32 b). warp w handles n0+w over 32 b.
__global__ void __launch_bounds__(256) k_apass(int mode) {
    const float* sIn = (mode == 0) ? g_S0 : g_s1;
    float sscale = (mode == 0) ? (1.0f / NN) : 1.0f;
    float* bOut = (mode == 0) ? g_b1 : g_b2;

    __shared__ float vs[32 * LL];   // v for this CTA's 32 b (8 KB)
    int t = threadIdx.x;
    int nt = blockIdx.x >> 2, bq = blockIdx.x & 3;
    int b0 = bq * 32;

    {   // vs = squash(sIn[b0..b0+32, :]*scale)
        const float4* sp = reinterpret_cast<const float4*>(sIn) + b0 * (LL / 4);
        float4* vp4 = reinterpret_cast<float4*>(vs);
        for (int i = t; i < 32 * LL / 4; i += 256) {
            float4 a = sp[i];
            vp4[i] = make_float4(squashf(a.x * sscale), squashf(a.y * sscale),
                                 squashf(a.z * sscale), squashf(a.w * sscale));
        }
    }
    __syncthreads();

    int w = t >> 5, lane = t & 31;
    int n = nt * 8 + w;
    const float2* up = reinterpret_cast<const float2*>(g_uhat + ((size_t)n * BB + b0) * LL) + lane;
    const float2* vp = reinterpret_cast<const float2*>(vs) + lane;
    float acc = 0.f;
#pragma unroll 8
    for (int b = 0; b < 32; b++) {
        float2 u = up[b * 32];
        float2 vv = vp[b * 32];
        acc += u.x * vv.x + u.y * vv.y;
    }
#pragma unroll
    for (int off = 16; off; off >>= 1) acc += __shfl_xor_sync(0xffffffffu, acc, off);
    if (lane == 0) {
        acc *= (1.0f / BB);
        if (mode == 1 && bq == 0) acc += g_b1[n];   // b2 = b1 + mean
        atomicAdd(&bOut[n], acc);
    }
}

// ---------------- s-pass ----------------
// c = softmax(bIn) (per-CTA recompute); sOut[b,l] += sum_{n in tile} c[n]*u_hat[n,b,l]
// grid 1296 = 324 n-tiles (8 n) x 4 b-tiles (32 b). mode==1: bq==0 CTAs export c -> g_c2.
__global__ void __launch_bounds__(256) k_spass(int mode) {
    const float* bIn = (mode == 0) ? g_b1 : g_b2;
    float* sOut = (mode == 0) ? g_s1 : g_s2;

    __shared__ float red[256];
    __shared__ float cs[8];
    int t = threadIdx.x;
    int nt = blockIdx.x >> 2, bq = blockIdx.x & 3;
    int n0 = nt * 8, b0 = bq * 32;

    float m = -3.0e38f;
    for (int i = t; i < NN; i += 256) m = fmaxf(m, bIn[i]);
    red[t] = m; __syncthreads();
    for (int s = 128; s; s >>= 1) { if (t < s) red[t] = fmaxf(red[t], red[t + s]); __syncthreads(); }
    float mx = red[0]; __syncthreads();

    float sm = 0.f;
    for (int i = t; i < NN; i += 256) sm += __expf(bIn[i] - mx);
    red[t] = sm; __syncthreads();
    for (int s = 128; s; s >>= 1) { if (t < s) red[t] += red[t + s]; __syncthreads(); }
    float denom = red[0]; __syncthreads();

    if (t < 8) {
        float c = __expf(bIn[n0 + t] - mx) / denom;
        cs[t] = c;
        if (mode == 1 && bq == 0) g_c2[n0 + t] = c;
    }
    __syncthreads();

    // thread -> (bl = t>>3 in [0,32), l4 = t&7): two float4 per n
    int bl = t >> 3, l4 = t & 7;
    float a0x = 0.f, a0y = 0.f, a0z = 0.f, a0w = 0.f;
    float a1x = 0.f, a1y = 0.f, a1z = 0.f, a1w = 0.f;
#pragma unroll
    for (int nn = 0; nn < 8; nn++) {
        float cv = cs[nn];
        const float4* p = reinterpret_cast<const float4*>(
            g_uhat + ((size_t)(n0 + nn) * BB + b0 + bl) * LL);
        float4 u0 = p[l4 * 2], u1 = p[l4 * 2 + 1];
        a0x += cv * u0.x; a0y += cv * u0.y; a0z += cv * u0.z; a0w += cv * u0.w;
        a1x += cv * u1.x; a1y += cv * u1.y; a1z += cv * u1.z; a1w += cv * u1.w;
    }
    float* dst = sOut + (b0 + bl) * LL + l4 * 8;
    red_add_v4(dst, a0x, a0y, a0z, a0w);
    red_add_v4(dst + 4, a1x, a1y, a1z, a1w);
}

// ---------------- K6: v_j output + ConvTranspose2d ----------------
// blocks [0,2048): (b,oh) conv tiles; un computed from c2*sqrt(nrm2).
// blocks [2048,2080): v_j = squash(s2).
__global__ void __launch_bounds__(256) k6_out(const float* __restrict__ cw,
                                              const float* __restrict__ cb,
                                              float* __restrict__ out) {
    int t = threadIdx.x;
    if (blockIdx.x >= 2048) {
        int idx = (blockIdx.x - 2048) * 256 + t;   // 32*256 = 8192
        out[idx] = squashf(g_s2[idx]);
        return;
    }
    int b = blockIdx.x >> 4, oh = blockIdx.x & 15;
    __shared__ float ws[32][64][2];   // ws[ic][oc][j] = conv_w[ic][oc][1-kh][j]
    __shared__ float un[32][9];
    __shared__ float bias[CHO];

    int kh = oh & 1;
    int ih = (oh + kh) >> 1;

    for (int i = t; i < 32 * 64 * 2; i += 256) {
        int ic = i >> 7, r = i & 127, oc = r >> 1, j = r & 1;
        ws[ic][oc][j] = cw[ic * 256 + oc * 4 + (1 - kh) * 2 + j];
    }
    for (int i = t; i < 288; i += 256) {
        int ic = i / 9, iw = i - ic * 9;
        int n = ic * 81 + ih * 9 + iw;
        un[ic][iw] = g_c2[n] * sqrtf(g_nrm2[(size_t)n * BB + b]);
    }
    if (t < CHO) bias[t] = cb[t];
    __syncthreads();

    int ow = t & 15, ocg = t >> 4;
    int kw = ow & 1;
    int iw = (ow + kw) >> 1;
    int j = 1 - kw;
    size_t obase = 8192 + (((size_t)b * CHO) * 16 + oh) * 16 + ow;
#pragma unroll
    for (int q = 0; q < 4; q++) {
        int oc = ocg * 4 + q;
        float acc = bias[oc];
#pragma unroll
        for (int ic = 0; ic < 32; ic++) acc += un[ic][iw] * ws[ic][oc][j];
        out[obase + (size_t)oc * 256] = acc;
    }
}

// ---------------- launch ----------------
extern "C" void kernel_launch(void* const* d_in, const int* in_sizes, int n_in,
                              void* d_out, int out_size) {
    const float* x  = (const float*)d_in[0];   // (128, 2592, 16)
    const float* W  = (const float*)d_in[1];   // (1, 2592, 1, 64, 16)
    const float* cw = (const float*)d_in[2];   // (32, 64, 2, 2)
    const float* cb = (const float*)d_in[3];   // (64,)
    float* out = (float*)d_out;                // 8192 (v_j) + 2097152 (out_img)

    kzero<<<32, 256>>>();
    k1_uhat<<<648, 256>>>(x, W);    // u_hat + S0 + nrm2
    k_apass<<<1296, 256>>>(0);      // v0=squash(S0/N); b1 = mean_b <u_hat, v0>
    k_spass<<<1296, 256>>>(0);      // c1=softmax(b1); s1 = sum c1*u_hat
    k_apass<<<1296, 256>>>(1);      // v1=squash(s1);  b2 = b1 + mean_b <u_hat, v1>
    k_spass<<<1296, 256>>>(1);      // c2=softmax(b2); s2; export c2
    k6_out<<<2080, 256>>>(cw, cb, out);  // v_j = squash(s2); ConvT -> out_img
}

// round 6
// speedup vs baseline: 1.7412x; 1.1398x over previous
#include <cuda_runtime.h>
#include <cuda_fp16.h>
#include <math.h>

#define NN 2592
#define BB 128
#define LL 64
#define CC 16
#define CHO 64

// ---------------- scratch (device globals; no allocation) ----------------
__device__ __half g_uhatH[(size_t)NN * BB * LL]; // [n][b][l]  ~42.5 MB fp16
__device__ float g_S0[BB * LL];                  // sum_n u_hat (exact fp32)
__device__ float g_s1[BB * LL];
__device__ float g_s2[BB * LL];
__device__ float g_b1[NN];
__device__ float g_b2[NN];
__device__ float g_c2[NN];
__device__ float g_nrm2[(size_t)NN * BB];        // [n][b] : sum_l u_hat^2 (exact fp32)

struct alignas(8) h4pack { __half2 a, b; };

__device__ __forceinline__ float squashf(float s) {
    float sq = s * s;
    return s * fabsf(s) / (1.0f + sq);   // == sq*s/((1+sq)*sqrt(sq))
}

__device__ __forceinline__ void red_add_v4(float* p, float a, float b, float c, float d) {
    asm volatile("red.global.add.v4.f32 [%0], {%1, %2, %3, %4};"
                 :: "l"(p), "f"(a), "f"(b), "f"(c), "f"(d) : "memory");
}

// ---------------- K0: zero accumulators ----------------
__global__ void kzero() {
    int i = blockIdx.x * 256 + threadIdx.x;
    if (i < BB * LL) { g_S0[i] = 0.f; g_s1[i] = 0.f; g_s2[i] = 0.f; }
    if (i < NN) { g_b1[i] = 0.f; g_b2[i] = 0.f; }
}

// ---------------- K1: u_hat(fp16) + S0 (red.v4, fp32) + nrm2 (fp32) ----------------
// grid 648 (4 n per CTA), 256 threads. Per n: (128b x 64l) = x[:,n,:](128x16) @ W[n]^T(16x64)
__global__ void __launch_bounds__(256) k1_uhat(const float* __restrict__ x,
                                               const float* __restrict__ W) {
    __shared__ float xs[CC][BB];
    __shared__ float Ws[CC][LL];
    __shared__ float ps[CC][BB + 1];

    int t = threadIdx.x;
    int n0 = blockIdx.x * 4;
    int bg = t >> 4, lq = t & 15;
    int bbase = bg * 8;

    float s_acc[8][4];
#pragma unroll
    for (int i = 0; i < 8; i++)
#pragma unroll
        for (int j = 0; j < 4; j++) s_acc[i][j] = 0.f;

#pragma unroll 1
    for (int nn = 0; nn < 4; nn++) {
        int n = n0 + nn;
        {   // x[:, n, :] -> xs[c][b]
            int b = t & 127, half = t >> 7;
            const float4* xp = reinterpret_cast<const float4*>(x + ((size_t)b * NN + n) * CC) + half * 2;
            float4 a = xp[0], c4 = xp[1];
            int cb = half * 8;
            xs[cb + 0][b] = a.x;  xs[cb + 1][b] = a.y;  xs[cb + 2][b] = a.z;  xs[cb + 3][b] = a.w;
            xs[cb + 4][b] = c4.x; xs[cb + 5][b] = c4.y; xs[cb + 6][b] = c4.z; xs[cb + 7][b] = c4.w;
        }
        {   // W[n] -> Ws[c][l]
            int l = t & 63, cq = t >> 6;
            const float4* wp = reinterpret_cast<const float4*>(W + ((size_t)n * LL + l) * CC + cq * 4);
            float4 a = wp[0];
            Ws[cq * 4 + 0][l] = a.x; Ws[cq * 4 + 1][l] = a.y;
            Ws[cq * 4 + 2][l] = a.z; Ws[cq * 4 + 3][l] = a.w;
        }
        __syncthreads();

        float acc[8][4];
#pragma unroll
        for (int i = 0; i < 8; i++)
#pragma unroll
            for (int j = 0; j < 4; j++) acc[i][j] = 0.f;

#pragma unroll
        for (int c = 0; c < CC; c++) {
            float4 xa = *reinterpret_cast<const float4*>(&xs[c][bbase]);
            float4 xb = *reinterpret_cast<const float4*>(&xs[c][bbase + 4]);
            float4 wv = *reinterpret_cast<const float4*>(&Ws[c][lq * 4]);
            float xr[8] = {xa.x, xa.y, xa.z, xa.w, xb.x, xb.y, xb.z, xb.w};
            float wr[4] = {wv.x, wv.y, wv.z, wv.w};
#pragma unroll
            for (int i = 0; i < 8; i++)
#pragma unroll
                for (int j = 0; j < 4; j++) acc[i][j] += xr[i] * wr[j];
        }

        __half* ub = g_uhatH + (size_t)n * BB * LL;
#pragma unroll
        for (int i = 0; i < 8; i++) {
            int b = bbase + i;
            h4pack pk;
            pk.a = __floats2half2_rn(acc[i][0], acc[i][1]);
            pk.b = __floats2half2_rn(acc[i][2], acc[i][3]);
            *reinterpret_cast<h4pack*>(ub + b * LL + lq * 4) = pk;
            ps[lq][b] = acc[i][0] * acc[i][0] + acc[i][1] * acc[i][1] +
                        acc[i][2] * acc[i][2] + acc[i][3] * acc[i][3];
            s_acc[i][0] += acc[i][0]; s_acc[i][1] += acc[i][1];
            s_acc[i][2] += acc[i][2]; s_acc[i][3] += acc[i][3];
        }
        __syncthreads();
        if (t < BB) {
            float nr = 0.f;
#pragma unroll
            for (int q = 0; q < 16; q++) nr += ps[q][t];
            g_nrm2[(size_t)n * BB + t] = nr;
        }
        __syncthreads();
    }

#pragma unroll
    for (int i = 0; i < 8; i++)
        red_add_v4(&g_S0[(bbase + i) * LL + lq * 4],
                   s_acc[i][0], s_acc[i][1], s_acc[i][2], s_acc[i][3]);
}

// ---------------- a-pass ----------------
// b_out[n] += (1/B) * sum_{b in tile} <u_hat[b,n,:], v[b,:]>,  v = squash(sIn*scale)
// grid 1296 = 324 n-tiles (8 n) x 4 b-tiles (32 b). warp w handles n0+w over 32 b.
__global__ void __launch_bounds__(256) k_apass(int mode) {
    const float* sIn = (mode == 0) ? g_S0 : g_s1;
    float sscale = (mode == 0) ? (1.0f / NN) : 1.0f;
    float* bOut = (mode == 0) ? g_b1 : g_b2;

    __shared__ float vs[32 * LL];   // 8 KB
    int t = threadIdx.x;
    int nt = blockIdx.x >> 2, bq = blockIdx.x & 3;
    int b0 = bq * 32;

    {
        const float4* sp = reinterpret_cast<const float4*>(sIn) + b0 * (LL / 4);
        float4* vp4 = reinterpret_cast<float4*>(vs);
        for (int i = t; i < 32 * LL / 4; i += 256) {
            float4 a = sp[i];
            vp4[i] = make_float4(squashf(a.x * sscale), squashf(a.y * sscale),
                                 squashf(a.z * sscale), squashf(a.w * sscale));
        }
    }
    __syncthreads();

    int w = t >> 5, lane = t & 31;
    int n = nt * 8 + w;
    const __half2* up = reinterpret_cast<const __half2*>(g_uhatH + ((size_t)n * BB + b0) * LL) + lane;
    const float2* vp = reinterpret_cast<const float2*>(vs) + lane;
    float acc = 0.f;
#pragma unroll 8
    for (int b = 0; b < 32; b++) {
        float2 u = __half22float2(up[b * 32]);
        float2 vv = vp[b * 32];
        acc += u.x * vv.x + u.y * vv.y;
    }
#pragma unroll
    for (int off = 16; off; off >>= 1) acc += __shfl_xor_sync(0xffffffffu, acc, off);
    if (lane == 0) {
        acc *= (1.0f / BB);
        if (mode == 1 && bq == 0) acc += g_b1[n];   // b2 = b1 + mean
        atomicAdd(&bOut[n], acc);
    }
}

// ---------------- s-pass ----------------
// c = softmax(bIn) (per-CTA recompute, warp-shuffle); sOut[b,l] += sum_{n in tile} c[n]*u_hat
// grid 1296 = 324 n-tiles (8 n) x 4 b-tiles (32 b). mode==1: bq==0 CTAs export c -> g_c2.
__global__ void __launch_bounds__(256) k_spass(int mode) {
    const float* bIn = (mode == 0) ? g_b1 : g_b2;
    float* sOut = (mode == 0) ? g_s1 : g_s2;

    __shared__ float wred[8];
    __shared__ float cs[8];
    int t = threadIdx.x;
    int wid = t >> 5, lane = t & 31;
    int nt = blockIdx.x >> 2, bq = blockIdx.x & 3;
    int n0 = nt * 8, b0 = bq * 32;

    // softmax max
    float m = -3.0e38f;
    for (int i = t; i < NN; i += 256) m = fmaxf(m, bIn[i]);
#pragma unroll
    for (int off = 16; off; off >>= 1) m = fmaxf(m, __shfl_xor_sync(0xffffffffu, m, off));
    if (lane == 0) wred[wid] = m;
    __syncthreads();
    float mx = wred[0];
#pragma unroll
    for (int q = 1; q < 8; q++) mx = fmaxf(mx, wred[q]);
    __syncthreads();

    // softmax sum
    float sm = 0.f;
    for (int i = t; i < NN; i += 256) sm += __expf(bIn[i] - mx);
#pragma unroll
    for (int off = 16; off; off >>= 1) sm += __shfl_xor_sync(0xffffffffu, sm, off);
    if (lane == 0) wred[wid] = sm;
    __syncthreads();
    float denom = wred[0] + wred[1] + wred[2] + wred[3] +
                  wred[4] + wred[5] + wred[6] + wred[7];

    if (t < 8) {
        float c = __expf(bIn[n0 + t] - mx) / denom;
        cs[t] = c;
        if (mode == 1 && bq == 0) g_c2[n0 + t] = c;
    }
    __syncthreads();

    // thread -> (bl = t>>3 in [0,32), l4 = t&7): one uint4 (8 fp16) per n
    int bl = t >> 3, l4 = t & 7;
    float a0 = 0.f, a1 = 0.f, a2 = 0.f, a3 = 0.f;
    float a4 = 0.f, a5 = 0.f, a6 = 0.f, a7 = 0.f;
#pragma unroll
    for (int nn = 0; nn < 8; nn++) {
        float cv = cs[nn];
        const uint4* p = reinterpret_cast<const uint4*>(
            g_uhatH + ((size_t)(n0 + nn) * BB + b0 + bl) * LL);
        uint4 q = p[l4];
        float2 f0 = __half22float2(*reinterpret_cast<const __half2*>(&q.x));
        float2 f1 = __half22float2(*reinterpret_cast<const __half2*>(&q.y));
        float2 f2 = __half22float2(*reinterpret_cast<const __half2*>(&q.z));
        float2 f3 = __half22float2(*reinterpret_cast<const __half2*>(&q.w));
        a0 += cv * f0.x; a1 += cv * f0.y; a2 += cv * f1.x; a3 += cv * f1.y;
        a4 += cv * f2.x; a5 += cv * f2.y; a6 += cv * f3.x; a7 += cv * f3.y;
    }
    float* dst = sOut + (b0 + bl) * LL + l4 * 8;
    red_add_v4(dst, a0, a1, a2, a3);
    red_add_v4(dst + 4, a4, a5, a6, a7);
}

// ---------------- K6: v_j output + ConvTranspose2d ----------------
__global__ void __launch_bounds__(256) k6_out(const float* __restrict__ cw,
                                              const float* __restrict__ cb,
                                              float* __restrict__ out) {
    int t = threadIdx.x;
    if (blockIdx.x >= 2048) {
        int idx = (blockIdx.x - 2048) * 256 + t;   // 32*256 = 8192
        out[idx] = squashf(g_s2[idx]);
        return;
    }
    int b = blockIdx.x >> 4, oh = blockIdx.x & 15;
    __shared__ float ws[32][64][2];
    __shared__ float un[32][9];
    __shared__ float bias[CHO];

    int kh = oh & 1;
    int ih = (oh + kh) >> 1;

    for (int i = t; i < 32 * 64 * 2; i += 256) {
        int ic = i >> 7, r = i & 127, oc = r >> 1, j = r & 1;
        ws[ic][oc][j] = cw[ic * 256 + oc * 4 + (1 - kh) * 2 + j];
    }
    for (int i = t; i < 288; i += 256) {
        int ic = i / 9, iw = i - ic * 9;
        int n = ic * 81 + ih * 9 + iw;
        un[ic][iw] = g_c2[n] * sqrtf(g_nrm2[(size_t)n * BB + b]);
    }
    if (t < CHO) bias[t] = cb[t];
    __syncthreads();

    int ow = t & 15, ocg = t >> 4;
    int kw = ow & 1;
    int iw = (ow + kw) >> 1;
    int j = 1 - kw;
    size_t obase = 8192 + (((size_t)b * CHO) * 16 + oh) * 16 + ow;
#pragma unroll
    for (int q = 0; q < 4; q++) {
        int oc = ocg * 4 + q;
        float acc = bias[oc];
#pragma unroll
        for (int ic = 0; ic < 32; ic++) acc += un[ic][iw] * ws[ic][oc][j];
        out[obase + (size_t)oc * 256] = acc;
    }
}

// ---------------- launch ----------------
extern "C" void kernel_launch(void* const* d_in, const int* in_sizes, int n_in,
                              void* d_out, int out_size) {
    const float* x  = (const float*)d_in[0];   // (128, 2592, 16)
    const float* W  = (const float*)d_in[1];   // (1, 2592, 1, 64, 16)
    const float* cw = (const float*)d_in[2];   // (32, 64, 2, 2)
    const float* cb = (const float*)d_in[3];   // (64,)
    float* out = (float*)d_out;                // 8192 (v_j) + 2097152 (out_img)

    kzero<<<32, 256>>>();
    k1_uhat<<<648, 256>>>(x, W);    // u_hat(fp16) + S0 + nrm2
    k_apass<<<1296, 256>>>(0);      // v0=squash(S0/N); b1 = mean_b <u_hat, v0>
    k_spass<<<1296, 256>>>(0);      // c1=softmax(b1); s1 = sum c1*u_hat
    k_apass<<<1296, 256>>>(1);      // v1=squash(s1);  b2 = b1 + mean_b <u_hat, v1>
    k_spass<<<1296, 256>>>(1);      // c2=softmax(b2); s2; export c2
    k6_out<<<2080, 256>>>(cw, cb, out);  // v_j = squash(s2); ConvT -> out_img
}